// round 10
// baseline (speedup 1.0000x reference)
#include <cuda_runtime.h>
#include <cuda_bf16.h>

#define N_NODES    50000
#define N_EDGES    800000
#define IN_DIM     128
#define HID_DIM    64
#define OUT_DIM    64
#define NUM_GRAPHS 512
#define SCAN_T     1024

// ---------------- scratch (device globals; no allocations allowed) ----------------
__device__ __align__(16) int    g_degc  [N_NODES];        // per-dst edge count
__device__ __align__(16) int    g_cur   [N_NODES];        // fill cursor
__device__ __align__(16) int    g_row   [N_NODES + 1];    // CSR row offsets
__device__ __align__(16) float  g_dinv  [N_NODES];
__device__ __align__(16) float2 g_csr   [N_EDGES];        // {src (int bits), norm}
__device__ __align__(16) int    g_gstart[NUM_GRAPHS + 1]; // graph segment boundaries
__device__ __align__(16) float  g_h     [N_NODES * 64];   // GEMM output (both layers)
__device__ __align__(16) float  g_agg1  [N_NODES * 64];   // relu(agg) layer 1
__device__ __align__(16) float  g_agg2  [N_NODES * 64];   // relu(agg) layer 2

// ---------------- kernels ----------------
__global__ void __launch_bounds__(256) zero_kernel() {
    int i = blockIdx.x * blockDim.x + threadIdx.x;
    if (i < N_NODES) { g_degc[i] = 0; g_cur[i] = 0; }
}

// count edges per dst (int atomics only). Indices are INT32.
__global__ void __launch_bounds__(256) count_kernel(const int* __restrict__ ei) {
    int e = blockIdx.x * blockDim.x + threadIdx.x;
    if (e >= N_EDGES) return;
    atomicAdd(&g_degc[ei[N_EDGES + e]], 1);
}

// single-block exclusive scan of g_degc -> g_row; also computes g_dinv.
__global__ void __launch_bounds__(SCAN_T) scan_kernel() {
    __shared__ int sp[SCAN_T];
    int t = threadIdx.x;
    const int C = (N_NODES + SCAN_T - 1) / SCAN_T;   // 49
    int beg = t * C;
    int end = min(beg + C, N_NODES);
    int sum = 0;
    for (int i = beg; i < end; i++) sum += g_degc[i];
    sp[t] = sum;
    __syncthreads();
    for (int off = 1; off < SCAN_T; off <<= 1) {
        int v = (t >= off) ? sp[t - off] : 0;
        __syncthreads();
        sp[t] += v;
        __syncthreads();
    }
    int excl = sp[t] - sum;
    for (int i = beg; i < end; i++) {
        int c = g_degc[i];
        g_row[i]  = excl;
        g_dinv[i] = rsqrtf(fmaxf((float)c, 1.0f));
        excl += c;
    }
    if (t == SCAN_T - 1) g_row[N_NODES] = sp[SCAN_T - 1];
}

// counting-sort fill: CSR entry = {src bits, dinv[src]*dinv[dst]}.
// Also (first N_NODES threads) derive graph boundaries from sorted batch.
__global__ void __launch_bounds__(256) fill_kernel(const int* __restrict__ ei,
                                                   const int* __restrict__ batch) {
    int e = blockIdx.x * blockDim.x + threadIdx.x;
    if (e < N_NODES) {
        int b  = batch[e];
        int bp = (e == 0) ? -1 : batch[e - 1];
        for (int g = bp + 1; g <= b; g++) g_gstart[g] = e;
        if (e == N_NODES - 1)
            for (int g = b + 1; g <= NUM_GRAPHS; g++) g_gstart[g] = N_NODES;
    }
    if (e >= N_EDGES) return;
    int s = ei[e];
    int d = ei[N_EDGES + e];
    int pos = g_row[d] + atomicAdd(&g_cur[d], 1);
    g_csr[pos] = make_float2(__int_as_float(s), g_dinv[s] * g_dinv[d]);
}

// GEMM: g_h[M,64] = A[M,KTOT] @ W[KTOT,64] + bias
// 128x64 block tile, 8x4 register tile, K chunked at 32.
template<int KTOT, bool A_IS_AGG1>
__global__ void __launch_bounds__(256) gemm_kernel(const float* __restrict__ Ap,
                                                   const float* __restrict__ W,
                                                   const float* __restrict__ bias) {
    __shared__ float sA[128 * 36];   // padded stride 36 -> conflict-free column reads
    __shared__ float sW[32 * 64];

    const float* A = A_IS_AGG1 ? g_agg1 : Ap;
    int tid  = threadIdx.x;
    int row0 = blockIdx.x * 128;
    int ty   = tid >> 4;     // 0..15 -> 8 rows each
    int tx   = tid & 15;     // 0..15 -> 4 cols each

    float acc[8][4];
#pragma unroll
    for (int i = 0; i < 8; i++)
#pragma unroll
        for (int j = 0; j < 4; j++) acc[i][j] = 0.f;

    for (int k0 = 0; k0 < KTOT; k0 += 32) {
        // sA: 128 rows x 32 k = 1024 float4, 4 per thread
#pragma unroll
        for (int i = 0; i < 4; i++) {
            int idx = tid + i * 256;
            int r   = idx >> 3;          // 0..127
            int kc  = idx & 7;           // 0..7
            float4 v = make_float4(0.f, 0.f, 0.f, 0.f);
            int gr = row0 + r;
            if (gr < N_NODES)
                v = *(const float4*)(A + (size_t)gr * KTOT + k0 + kc * 4);
            *(float4*)(sA + r * 36 + kc * 4) = v;
        }
        // sW: 32 k x 64 c = 512 float4, 2 per thread
#pragma unroll
        for (int i = 0; i < 2; i++) {
            int idx = tid + i * 256;
            int kr  = idx >> 4;          // 0..31
            int cc  = idx & 15;          // 0..15
            *(float4*)(sW + kr * 64 + cc * 4) =
                *(const float4*)(W + (size_t)(k0 + kr) * 64 + cc * 4);
        }
        __syncthreads();

#pragma unroll
        for (int k = 0; k < 32; k++) {
            float4 w = *(const float4*)(sW + k * 64 + tx * 4);
#pragma unroll
            for (int i = 0; i < 8; i++) {
                float a = sA[(ty * 8 + i) * 36 + k];
                acc[i][0] += a * w.x;
                acc[i][1] += a * w.y;
                acc[i][2] += a * w.z;
                acc[i][3] += a * w.w;
            }
        }
        __syncthreads();
    }

    float4 bv = *(const float4*)(bias + tx * 4);
#pragma unroll
    for (int i = 0; i < 8; i++) {
        int gr = row0 + ty * 8 + i;
        if (gr < N_NODES) {
            float4 o = make_float4(acc[i][0] + bv.x, acc[i][1] + bv.y,
                                   acc[i][2] + bv.z, acc[i][3] + bv.w);
            *(float4*)(g_h + (size_t)gr * 64 + tx * 4) = o;
        }
    }
}

// pull aggregation: one warp per node; half-warps process edge pairs.
// Lanes 0-15 handle edge e (float4 over 64 dims), lanes 16-31 handle edge e+1.
// Final shfl_xor(16) combines the two partial sums. No atomics.
template<bool TO_AGG2>
__global__ void __launch_bounds__(256) agg_kernel() {
    int warp = (blockIdx.x * 256 + threadIdx.x) >> 5;
    if (warp >= N_NODES) return;
    int lane = threadIdx.x & 31;
    int half = lane >> 4;        // 0 or 1
    int l16  = lane & 15;        // dim group: floats l16*4..l16*4+3
    int s0 = g_row[warp];
    int s1 = g_row[warp + 1];

    float4 acc0 = make_float4(0.f, 0.f, 0.f, 0.f);
    float4 acc1 = make_float4(0.f, 0.f, 0.f, 0.f);
    int e = s0;
    for (; e + 3 < s1; e += 4) {                    // 4 edges/iter (2 per half)
        float2 m0 = g_csr[e + half];
        float2 m1 = g_csr[e + 2 + half];
        float4 v0 = *(const float4*)(g_h + (size_t)__float_as_int(m0.x) * 64 + l16 * 4);
        float4 v1 = *(const float4*)(g_h + (size_t)__float_as_int(m1.x) * 64 + l16 * 4);
        acc0.x += v0.x * m0.y; acc0.y += v0.y * m0.y;
        acc0.z += v0.z * m0.y; acc0.w += v0.w * m0.y;
        acc1.x += v1.x * m1.y; acc1.y += v1.y * m1.y;
        acc1.z += v1.z * m1.y; acc1.w += v1.w * m1.y;
    }
    for (; e < s1; e += 2) {                        // remainder (0..3 edges)
        int idx = e + half;
        if (idx < s1) {
            float2 m = g_csr[idx];
            float4 v = *(const float4*)(g_h + (size_t)__float_as_int(m.x) * 64 + l16 * 4);
            acc0.x += v.x * m.y; acc0.y += v.y * m.y;
            acc0.z += v.z * m.y; acc0.w += v.w * m.y;
        }
    }
    acc0.x += acc1.x; acc0.y += acc1.y; acc0.z += acc1.z; acc0.w += acc1.w;
    // combine the two half-warp partials
    acc0.x += __shfl_xor_sync(0xffffffffu, acc0.x, 16);
    acc0.y += __shfl_xor_sync(0xffffffffu, acc0.y, 16);
    acc0.z += __shfl_xor_sync(0xffffffffu, acc0.z, 16);
    acc0.w += __shfl_xor_sync(0xffffffffu, acc0.w, 16);
    if (half == 0) {
        float4 r = make_float4(fmaxf(acc0.x, 0.f), fmaxf(acc0.y, 0.f),
                               fmaxf(acc0.z, 0.f), fmaxf(acc0.w, 0.f));
        float* dst = TO_AGG2 ? g_agg2 : g_agg1;
        *(float4*)(dst + (size_t)warp * 64 + l16 * 4) = r;
    }
}

// pooling: one block per graph over its contiguous node range; mean of g_agg2.
__global__ void __launch_bounds__(256) pool_kernel(float* __restrict__ out) {
    __shared__ float sm[256];
    int g = blockIdx.x;
    int t = threadIdx.x;
    int d = t & 63;
    int r = t >> 6;        // 0..3
    int s0 = g_gstart[g];
    int s1 = g_gstart[g + 1];
    float acc = 0.f;
    for (int n = s0 + r; n < s1; n += 4)
        acc += g_agg2[(size_t)n * 64 + d];
    sm[t] = acc;
    __syncthreads();
    if (t < 64) {
        float v = sm[t] + sm[t + 64] + sm[t + 128] + sm[t + 192];
        float c = (float)(s1 - s0);
        out[(size_t)g * 64 + t] = v / fmaxf(c, 1.0f);
    }
}

// ---------------- launch ----------------
extern "C" void kernel_launch(void* const* d_in, const int* in_sizes, int n_in,
                              void* d_out, int out_size) {
    // Identify inputs by element count (robust to metadata ordering).
    const float *x = nullptr, *W1 = nullptr, *b1 = nullptr, *W2 = nullptr, *b2 = nullptr;
    const int   *ei = nullptr, *batch = nullptr;
    for (int i = 0; i < n_in; i++) {
        switch (in_sizes[i]) {
            case N_NODES * IN_DIM:   x     = (const float*)d_in[i]; break;
            case 2 * N_EDGES:        ei    = (const int*)d_in[i];   break;
            case N_NODES:            batch = (const int*)d_in[i];   break;
            case IN_DIM * HID_DIM:   W1    = (const float*)d_in[i]; break;
            case HID_DIM * OUT_DIM:  W2    = (const float*)d_in[i]; break;
            case HID_DIM:
                if (!b1) b1 = (const float*)d_in[i];
                else     b2 = (const float*)d_in[i];
                break;
            default: break;
        }
    }
    float* out = (float*)d_out;

    const int T = 256;
    zero_kernel <<<(N_NODES + T - 1) / T, T>>>();
    count_kernel<<<(N_EDGES + T - 1) / T, T>>>(ei);
    scan_kernel <<<1, SCAN_T>>>();
    fill_kernel <<<(N_EDGES + T - 1) / T, T>>>(ei, batch);

    // layer 1: h = x @ W1 + b1; agg1 = relu(pull-agg(h))
    gemm_kernel<IN_DIM, false><<<(N_NODES + 127) / 128, T>>>(x, W1, b1);
    agg_kernel<false><<<(N_NODES * 32 + T - 1) / T, T>>>();

    // layer 2: h = agg1 @ W2 + b2; agg2 = relu(pull-agg(h))
    gemm_kernel<HID_DIM, true><<<(N_NODES + 127) / 128, T>>>(nullptr, W2, b2);
    agg_kernel<true><<<(N_NODES * 32 + T - 1) / T, T>>>();

    // pooling: mean over each graph's contiguous node segment
    pool_kernel<<<NUM_GRAPHS, T>>>(out);
}

// round 11
// speedup vs baseline: 1.0574x; 1.0574x over previous
#include <cuda_runtime.h>
#include <cuda_bf16.h>

#define N_NODES    50000
#define N_EDGES    800000
#define IN_DIM     128
#define HID_DIM    64
#define OUT_DIM    64
#define NUM_GRAPHS 512
#define SCAN_T     1024

// ---------------- scratch (device globals; no allocations allowed) ----------------
__device__ __align__(16) int    g_degc  [N_NODES];        // per-dst edge count
__device__ __align__(16) int    g_cur   [N_NODES];        // fill cursor
__device__ __align__(16) int    g_row   [N_NODES + 1];    // CSR row offsets
__device__ __align__(16) float  g_dinv  [N_NODES];
__device__ __align__(16) int    g_srci  [N_EDGES];        // CSR payload: src index only
__device__ __align__(16) int    g_gstart[NUM_GRAPHS + 1]; // graph segment boundaries
__device__ __align__(16) float  g_h     [N_NODES * 64];   // (A@W+b)*dinv[row], both layers
__device__ __align__(16) float  g_agg1  [N_NODES * 64];   // relu(agg) layer 1
__device__ __align__(16) float  g_agg2  [N_NODES * 64];   // relu(agg) layer 2

// ---------------- kernels ----------------
__global__ void __launch_bounds__(256) zero_kernel() {
    int i = blockIdx.x * blockDim.x + threadIdx.x;
    if (i < N_NODES) { g_degc[i] = 0; g_cur[i] = 0; }
}

// count edges per dst (int atomics only). Indices are INT32.
__global__ void __launch_bounds__(256) count_kernel(const int* __restrict__ ei) {
    int e = blockIdx.x * blockDim.x + threadIdx.x;
    if (e >= N_EDGES) return;
    atomicAdd(&g_degc[ei[N_EDGES + e]], 1);
}

// single-block exclusive scan of g_degc -> g_row; also computes g_dinv.
__global__ void __launch_bounds__(SCAN_T) scan_kernel() {
    __shared__ int sp[SCAN_T];
    int t = threadIdx.x;
    const int C = (N_NODES + SCAN_T - 1) / SCAN_T;   // 49
    int beg = t * C;
    int end = min(beg + C, N_NODES);
    int sum = 0;
    for (int i = beg; i < end; i++) sum += g_degc[i];
    sp[t] = sum;
    __syncthreads();
    for (int off = 1; off < SCAN_T; off <<= 1) {
        int v = (t >= off) ? sp[t - off] : 0;
        __syncthreads();
        sp[t] += v;
        __syncthreads();
    }
    int excl = sp[t] - sum;
    for (int i = beg; i < end; i++) {
        int c = g_degc[i];
        g_row[i]  = excl;
        g_dinv[i] = rsqrtf(fmaxf((float)c, 1.0f));
        excl += c;
    }
    if (t == SCAN_T - 1) g_row[N_NODES] = sp[SCAN_T - 1];
}

// counting-sort fill: CSR payload = src only (norm is factored out).
// Also (first N_NODES threads) derive graph boundaries from sorted batch.
__global__ void __launch_bounds__(256) fill_kernel(const int* __restrict__ ei,
                                                   const int* __restrict__ batch) {
    int e = blockIdx.x * blockDim.x + threadIdx.x;
    if (e < N_NODES) {
        int b  = batch[e];
        int bp = (e == 0) ? -1 : batch[e - 1];
        for (int g = bp + 1; g <= b; g++) g_gstart[g] = e;
        if (e == N_NODES - 1)
            for (int g = b + 1; g <= NUM_GRAPHS; g++) g_gstart[g] = N_NODES;
    }
    if (e >= N_EDGES) return;
    int s = ei[e];
    int d = ei[N_EDGES + e];
    int pos = g_row[d] + atomicAdd(&g_cur[d], 1);
    g_srci[pos] = s;
}

// GEMM: g_h[M,64] = ((A[M,KTOT] @ W[KTOT,64]) + bias) * dinv[row]
// 64x64 block tile, 4x4 register tile, K chunked at 64 (round-9 proven config).
template<int KTOT, bool A_IS_AGG1>
__global__ void __launch_bounds__(256) gemm_kernel(const float* __restrict__ Ap,
                                                   const float* __restrict__ W,
                                                   const float* __restrict__ bias) {
    __shared__ float sA[64 * 68];   // stride 68 -> conflict-free column reads
    __shared__ float sW[64 * 64];

    const float* A = A_IS_AGG1 ? g_agg1 : Ap;
    int tid  = threadIdx.x;
    int row0 = blockIdx.x * 64;
    int ty   = tid >> 4;     // 0..15
    int tx   = tid & 15;     // 0..15

    float acc[4][4];
#pragma unroll
    for (int i = 0; i < 4; i++)
#pragma unroll
        for (int j = 0; j < 4; j++) acc[i][j] = 0.f;

    for (int k0 = 0; k0 < KTOT; k0 += 64) {
#pragma unroll
        for (int t = tid; t < 64 * 16; t += 256) {
            int r  = t >> 4;
            int kc = t & 15;
            float4 v = make_float4(0.f, 0.f, 0.f, 0.f);
            int gr = row0 + r;
            if (gr < N_NODES)
                v = *(const float4*)(A + (size_t)gr * KTOT + k0 + kc * 4);
            *(float4*)(sA + r * 68 + kc * 4) = v;
        }
#pragma unroll
        for (int t = tid; t < 64 * 16; t += 256) {
            int kr = t >> 4;
            int cc = t & 15;
            *(float4*)(sW + kr * 64 + cc * 4) =
                *(const float4*)(W + (size_t)(k0 + kr) * 64 + cc * 4);
        }
        __syncthreads();

#pragma unroll
        for (int k = 0; k < 64; k++) {
            float a0 = sA[(ty * 4 + 0) * 68 + k];
            float a1 = sA[(ty * 4 + 1) * 68 + k];
            float a2 = sA[(ty * 4 + 2) * 68 + k];
            float a3 = sA[(ty * 4 + 3) * 68 + k];
            float4 w = *(const float4*)(sW + k * 64 + tx * 4);
            acc[0][0] += a0 * w.x; acc[0][1] += a0 * w.y; acc[0][2] += a0 * w.z; acc[0][3] += a0 * w.w;
            acc[1][0] += a1 * w.x; acc[1][1] += a1 * w.y; acc[1][2] += a1 * w.z; acc[1][3] += a1 * w.w;
            acc[2][0] += a2 * w.x; acc[2][1] += a2 * w.y; acc[2][2] += a2 * w.z; acc[2][3] += a2 * w.w;
            acc[3][0] += a3 * w.x; acc[3][1] += a3 * w.y; acc[3][2] += a3 * w.z; acc[3][3] += a3 * w.w;
        }
        __syncthreads();
    }

    float4 bv = *(const float4*)(bias + tx * 4);
#pragma unroll
    for (int i = 0; i < 4; i++) {
        int gr = row0 + ty * 4 + i;
        if (gr < N_NODES) {
            float dv = g_dinv[gr];
            float4 o = make_float4((acc[i][0] + bv.x) * dv, (acc[i][1] + bv.y) * dv,
                                   (acc[i][2] + bv.z) * dv, (acc[i][3] + bv.w) * dv);
            *(float4*)(g_h + (size_t)gr * 64 + tx * 4) = o;
        }
    }
}

// pull aggregation: one warp per node; lane owns 2 dims (float2).
// agg[n] = relu( dinv[n] * sum_{e in CSR[n]} h[src_e] ).  h already carries dinv[src].
// 4-edge unroll for MLP=4.  No atomics.
template<bool TO_AGG2>
__global__ void __launch_bounds__(256) agg_kernel() {
    int node = (blockIdx.x * 256 + threadIdx.x) >> 5;
    if (node >= N_NODES) return;
    int lane = threadIdx.x & 31;
    int s0 = g_row[node];
    int s1 = g_row[node + 1];

    float2 a0 = make_float2(0.f, 0.f);
    float2 a1 = make_float2(0.f, 0.f);
    float2 a2 = make_float2(0.f, 0.f);
    float2 a3 = make_float2(0.f, 0.f);
    int e = s0;
    for (; e + 3 < s1; e += 4) {
        int i0 = g_srci[e + 0];
        int i1 = g_srci[e + 1];
        int i2 = g_srci[e + 2];
        int i3 = g_srci[e + 3];
        float2 v0 = *(const float2*)(g_h + (size_t)i0 * 64 + lane * 2);
        float2 v1 = *(const float2*)(g_h + (size_t)i1 * 64 + lane * 2);
        float2 v2 = *(const float2*)(g_h + (size_t)i2 * 64 + lane * 2);
        float2 v3 = *(const float2*)(g_h + (size_t)i3 * 64 + lane * 2);
        a0.x += v0.x; a0.y += v0.y;
        a1.x += v1.x; a1.y += v1.y;
        a2.x += v2.x; a2.y += v2.y;
        a3.x += v3.x; a3.y += v3.y;
    }
    for (; e < s1; e++) {
        int i0 = g_srci[e];
        float2 v0 = *(const float2*)(g_h + (size_t)i0 * 64 + lane * 2);
        a0.x += v0.x; a0.y += v0.y;
    }
    float dv = g_dinv[node];
    float sx = ((a0.x + a1.x) + (a2.x + a3.x)) * dv;
    float sy = ((a0.y + a1.y) + (a2.y + a3.y)) * dv;
    float2 r = make_float2(fmaxf(sx, 0.f), fmaxf(sy, 0.f));
    float* dst = TO_AGG2 ? g_agg2 : g_agg1;
    *(float2*)(dst + (size_t)node * 64 + lane * 2) = r;
}

// pooling: one block per graph over its contiguous node range; mean of g_agg2.
__global__ void __launch_bounds__(256) pool_kernel(float* __restrict__ out) {
    __shared__ float sm[256];
    int g = blockIdx.x;
    int t = threadIdx.x;
    int d = t & 63;
    int r = t >> 6;        // 0..3
    int s0 = g_gstart[g];
    int s1 = g_gstart[g + 1];
    float acc = 0.f;
    for (int n = s0 + r; n < s1; n += 4)
        acc += g_agg2[(size_t)n * 64 + d];
    sm[t] = acc;
    __syncthreads();
    if (t < 64) {
        float v = sm[t] + sm[t + 64] + sm[t + 128] + sm[t + 192];
        float c = (float)(s1 - s0);
        out[(size_t)g * 64 + t] = v / fmaxf(c, 1.0f);
    }
}

// ---------------- launch ----------------
extern "C" void kernel_launch(void* const* d_in, const int* in_sizes, int n_in,
                              void* d_out, int out_size) {
    // Identify inputs by element count (robust to metadata ordering).
    const float *x = nullptr, *W1 = nullptr, *b1 = nullptr, *W2 = nullptr, *b2 = nullptr;
    const int   *ei = nullptr, *batch = nullptr;
    for (int i = 0; i < n_in; i++) {
        switch (in_sizes[i]) {
            case N_NODES * IN_DIM:   x     = (const float*)d_in[i]; break;
            case 2 * N_EDGES:        ei    = (const int*)d_in[i];   break;
            case N_NODES:            batch = (const int*)d_in[i];   break;
            case IN_DIM * HID_DIM:   W1    = (const float*)d_in[i]; break;
            case HID_DIM * OUT_DIM:  W2    = (const float*)d_in[i]; break;
            case HID_DIM:
                if (!b1) b1 = (const float*)d_in[i];
                else     b2 = (const float*)d_in[i];
                break;
            default: break;
        }
    }
    float* out = (float*)d_out;

    const int T = 256;
    zero_kernel <<<(N_NODES + T - 1) / T, T>>>();
    count_kernel<<<(N_EDGES + T - 1) / T, T>>>(ei);
    scan_kernel <<<1, SCAN_T>>>();
    fill_kernel <<<(N_EDGES + T - 1) / T, T>>>(ei, batch);

    // layer 1: h = (x @ W1 + b1)*dinv; agg1 = relu(dinv * pull-sum(h))
    gemm_kernel<IN_DIM, false><<<(N_NODES + 63) / 64, T>>>(x, W1, b1);
    agg_kernel<false><<<(N_NODES * 32 + T - 1) / T, T>>>();

    // layer 2: h = (agg1 @ W2 + b2)*dinv; agg2 = relu(dinv * pull-sum(h))
    gemm_kernel<HID_DIM, true><<<(N_NODES + 63) / 64, T>>>(nullptr, W2, b2);
    agg_kernel<true><<<(N_NODES * 32 + T - 1) / T, T>>>();

    // pooling: mean over each graph's contiguous node segment
    pool_kernel<<<NUM_GRAPHS, T>>>(out);
}

// round 13
// speedup vs baseline: 1.0600x; 1.0025x over previous
#include <cuda_runtime.h>
#include <cuda_fp16.h>

#define N_NODES    50000
#define N_EDGES    800000
#define IN_DIM     128
#define HID_DIM    64
#define OUT_DIM    64
#define NUM_GRAPHS 512
#define SCAN_T     1024

// ---------------- scratch (device globals; no allocations allowed) ----------------
__device__ __align__(16) int     g_degc  [N_NODES];        // per-dst edge count
__device__ __align__(16) int     g_cur   [N_NODES];        // fill cursor
__device__ __align__(16) int     g_row   [N_NODES + 1];    // CSR row offsets
__device__ __align__(16) float   g_dinv  [N_NODES];
__device__ __align__(16) int     g_srci  [N_EDGES];        // CSR payload: src index only
__device__ __align__(16) int     g_gstart[NUM_GRAPHS + 1]; // graph segment boundaries
__device__ __align__(16) __half2 g_hh    [N_NODES * 32];   // fp16 h = (A@W+b)*dinv[row]
__device__ __align__(16) float   g_agg1  [N_NODES * 64];   // relu(agg) layer 1 (fp32)
__device__ __align__(16) float   g_agg2  [N_NODES * 64];   // relu(agg) layer 2 (fp32)

// ---------------- kernels ----------------
// count edges per dst (int atomics only). Indices are INT32.
__global__ void __launch_bounds__(256) count_kernel(const int* __restrict__ ei) {
    int e = blockIdx.x * blockDim.x + threadIdx.x;
    if (e >= N_EDGES) return;
    atomicAdd(&g_degc[ei[N_EDGES + e]], 1);
}

// single-block exclusive scan of g_degc -> g_row; also computes g_dinv.
__global__ void __launch_bounds__(SCAN_T) scan_kernel() {
    __shared__ int sp[SCAN_T];
    int t = threadIdx.x;
    const int C = (N_NODES + SCAN_T - 1) / SCAN_T;   // 49
    int beg = t * C;
    int end = min(beg + C, N_NODES);
    int sum = 0;
    for (int i = beg; i < end; i++) sum += g_degc[i];
    sp[t] = sum;
    __syncthreads();
    for (int off = 1; off < SCAN_T; off <<= 1) {
        int v = (t >= off) ? sp[t - off] : 0;
        __syncthreads();
        sp[t] += v;
        __syncthreads();
    }
    int excl = sp[t] - sum;
    for (int i = beg; i < end; i++) {
        int c = g_degc[i];
        g_row[i]  = excl;
        g_dinv[i] = rsqrtf(fmaxf((float)c, 1.0f));
        excl += c;
    }
    if (t == SCAN_T - 1) g_row[N_NODES] = sp[SCAN_T - 1];
}

// counting-sort fill: CSR payload = src only (norm is factored out).
// Also (first N_NODES threads) derive graph boundaries from sorted batch.
__global__ void __launch_bounds__(256) fill_kernel(const int* __restrict__ ei,
                                                   const int* __restrict__ batch) {
    int e = blockIdx.x * blockDim.x + threadIdx.x;
    if (e < N_NODES) {
        int b  = batch[e];
        int bp = (e == 0) ? -1 : batch[e - 1];
        for (int g = bp + 1; g <= b; g++) g_gstart[g] = e;
        if (e == N_NODES - 1)
            for (int g = b + 1; g <= NUM_GRAPHS; g++) g_gstart[g] = N_NODES;
    }
    if (e >= N_EDGES) return;
    int s = ei[e];
    int d = ei[N_EDGES + e];
    int pos = g_row[d] + atomicAdd(&g_cur[d], 1);
    g_srci[pos] = s;
}

// GEMM: g_hh[M,64](fp16) = ((A[M,KTOT] @ W[KTOT,64]) + bias) * dinv[row]
// 64x64 block tile, 4x4 register tile, K chunked at 64.
template<int KTOT, bool A_IS_AGG1>
__global__ void __launch_bounds__(256) gemm_kernel(const float* __restrict__ Ap,
                                                   const float* __restrict__ W,
                                                   const float* __restrict__ bias) {
    __shared__ float sA[64 * 68];   // stride 68 -> conflict-free column reads
    __shared__ float sW[64 * 64];

    const float* A = A_IS_AGG1 ? g_agg1 : Ap;
    int tid  = threadIdx.x;
    int row0 = blockIdx.x * 64;
    int ty   = tid >> 4;     // 0..15
    int tx   = tid & 15;     // 0..15

    float acc[4][4];
#pragma unroll
    for (int i = 0; i < 4; i++)
#pragma unroll
        for (int j = 0; j < 4; j++) acc[i][j] = 0.f;

    for (int k0 = 0; k0 < KTOT; k0 += 64) {
#pragma unroll
        for (int t = tid; t < 64 * 16; t += 256) {
            int r  = t >> 4;
            int kc = t & 15;
            float4 v = make_float4(0.f, 0.f, 0.f, 0.f);
            int gr = row0 + r;
            if (gr < N_NODES)
                v = *(const float4*)(A + (size_t)gr * KTOT + k0 + kc * 4);
            *(float4*)(sA + r * 68 + kc * 4) = v;
        }
#pragma unroll
        for (int t = tid; t < 64 * 16; t += 256) {
            int kr = t >> 4;
            int cc = t & 15;
            *(float4*)(sW + kr * 64 + cc * 4) =
                *(const float4*)(W + (size_t)(k0 + kr) * 64 + cc * 4);
        }
        __syncthreads();

#pragma unroll
        for (int k = 0; k < 64; k++) {
            float a0 = sA[(ty * 4 + 0) * 68 + k];
            float a1 = sA[(ty * 4 + 1) * 68 + k];
            float a2 = sA[(ty * 4 + 2) * 68 + k];
            float a3 = sA[(ty * 4 + 3) * 68 + k];
            float4 w = *(const float4*)(sW + k * 64 + tx * 4);
            acc[0][0] += a0 * w.x; acc[0][1] += a0 * w.y; acc[0][2] += a0 * w.z; acc[0][3] += a0 * w.w;
            acc[1][0] += a1 * w.x; acc[1][1] += a1 * w.y; acc[1][2] += a1 * w.z; acc[1][3] += a1 * w.w;
            acc[2][0] += a2 * w.x; acc[2][1] += a2 * w.y; acc[2][2] += a2 * w.z; acc[2][3] += a2 * w.w;
            acc[3][0] += a3 * w.x; acc[3][1] += a3 * w.y; acc[3][2] += a3 * w.z; acc[3][3] += a3 * w.w;
        }
        __syncthreads();
    }

    float4 bv = *(const float4*)(bias + tx * 4);
#pragma unroll
    for (int i = 0; i < 4; i++) {
        int gr = row0 + ty * 4 + i;
        if (gr < N_NODES) {
            float dv = g_dinv[gr];
            __half2 h0 = __floats2half2_rn((acc[i][0] + bv.x) * dv,
                                           (acc[i][1] + bv.y) * dv);
            __half2 h1 = __floats2half2_rn((acc[i][2] + bv.z) * dv,
                                           (acc[i][3] + bv.w) * dv);
            // two half2s = 8B, aligned (byte offset gr*128 + tx*8)
            uint2 packed = make_uint2(*(unsigned*)&h0, *(unsigned*)&h1);
            *(uint2*)(g_hh + (size_t)gr * 32 + tx * 2) = packed;
        }
    }
}

// pull aggregation: one warp per node; lane owns 2 dims (one half2 = 4B gather).
// agg[n] = relu( dinv[n] * sum_{e in CSR[n]} h[src_e] ).  h carries dinv[src].
// 4-edge unroll for MLP=4.  No atomics.  Accumulation in fp32.
template<bool TO_AGG2>
__global__ void __launch_bounds__(256) agg_kernel() {
    int node = (blockIdx.x * 256 + threadIdx.x) >> 5;
    if (node >= N_NODES) return;
    int lane = threadIdx.x & 31;
    int s0 = g_row[node];
    int s1 = g_row[node + 1];

    float2 a0 = make_float2(0.f, 0.f);
    float2 a1 = make_float2(0.f, 0.f);
    float2 a2 = make_float2(0.f, 0.f);
    float2 a3 = make_float2(0.f, 0.f);
    int e = s0;
    for (; e + 3 < s1; e += 4) {
        int i0 = g_srci[e + 0];
        int i1 = g_srci[e + 1];
        int i2 = g_srci[e + 2];
        int i3 = g_srci[e + 3];
        float2 v0 = __half22float2(g_hh[(size_t)i0 * 32 + lane]);
        float2 v1 = __half22float2(g_hh[(size_t)i1 * 32 + lane]);
        float2 v2 = __half22float2(g_hh[(size_t)i2 * 32 + lane]);
        float2 v3 = __half22float2(g_hh[(size_t)i3 * 32 + lane]);
        a0.x += v0.x; a0.y += v0.y;
        a1.x += v1.x; a1.y += v1.y;
        a2.x += v2.x; a2.y += v2.y;
        a3.x += v3.x; a3.y += v3.y;
    }
    for (; e < s1; e++) {
        float2 v = __half22float2(g_hh[(size_t)g_srci[e] * 32 + lane]);
        a0.x += v.x; a0.y += v.y;
    }
    float dv = g_dinv[node];
    float sx = ((a0.x + a1.x) + (a2.x + a3.x)) * dv;
    float sy = ((a0.y + a1.y) + (a2.y + a3.y)) * dv;
    float2 r = make_float2(fmaxf(sx, 0.f), fmaxf(sy, 0.f));
    float* dst = TO_AGG2 ? g_agg2 : g_agg1;
    *(float2*)(dst + (size_t)node * 64 + lane * 2) = r;
}

// pooling: one block per graph over its contiguous node range; mean of g_agg2.
__global__ void __launch_bounds__(256) pool_kernel(float* __restrict__ out) {
    __shared__ float sm[256];
    int g = blockIdx.x;
    int t = threadIdx.x;
    int d = t & 63;
    int r = t >> 6;        // 0..3
    int s0 = g_gstart[g];
    int s1 = g_gstart[g + 1];
    float acc = 0.f;
    for (int n = s0 + r; n < s1; n += 4)
        acc += g_agg2[(size_t)n * 64 + d];
    sm[t] = acc;
    __syncthreads();
    if (t < 64) {
        float v = sm[t] + sm[t + 64] + sm[t + 128] + sm[t + 192];
        float c = (float)(s1 - s0);
        out[(size_t)g * 64 + t] = v / fmaxf(c, 1.0f);
    }
}

// ---------------- launch ----------------
extern "C" void kernel_launch(void* const* d_in, const int* in_sizes, int n_in,
                              void* d_out, int out_size) {
    // Identify inputs by element count (robust to metadata ordering).
    const float *x = nullptr, *W1 = nullptr, *b1 = nullptr, *W2 = nullptr, *b2 = nullptr;
    const int   *ei = nullptr, *batch = nullptr;
    for (int i = 0; i < n_in; i++) {
        switch (in_sizes[i]) {
            case N_NODES * IN_DIM:   x     = (const float*)d_in[i]; break;
            case 2 * N_EDGES:        ei    = (const int*)d_in[i];   break;
            case N_NODES:            batch = (const int*)d_in[i];   break;
            case IN_DIM * HID_DIM:   W1    = (const float*)d_in[i]; break;
            case HID_DIM * OUT_DIM:  W2    = (const float*)d_in[i]; break;
            case HID_DIM:
                if (!b1) b1 = (const float*)d_in[i];
                else     b2 = (const float*)d_in[i];
                break;
            default: break;
        }
    }
    float* out = (float*)d_out;

    // zero the atomic counters via memset (graph-capturable, no extra kernel)
    void *degc_ptr = nullptr, *cur_ptr = nullptr;
    cudaGetSymbolAddress(&degc_ptr, g_degc);
    cudaGetSymbolAddress(&cur_ptr,  g_cur);
    cudaMemsetAsync(degc_ptr, 0, N_NODES * sizeof(int));
    cudaMemsetAsync(cur_ptr,  0, N_NODES * sizeof(int));

    const int T = 256;
    count_kernel<<<(N_EDGES + T - 1) / T, T>>>(ei);
    scan_kernel <<<1, SCAN_T>>>();
    fill_kernel <<<(N_EDGES + T - 1) / T, T>>>(ei, batch);

    // layer 1: h = (x @ W1 + b1)*dinv (fp16); agg1 = relu(dinv * pull-sum(h))
    gemm_kernel<IN_DIM, false><<<(N_NODES + 63) / 64, T>>>(x, W1, b1);
    agg_kernel<false><<<(N_NODES * 32 + T - 1) / T, T>>>();

    // layer 2: h = (agg1 @ W2 + b2)*dinv (fp16); agg2 = relu(dinv * pull-sum(h))
    gemm_kernel<HID_DIM, true><<<(N_NODES + 63) / 64, T>>>(nullptr, W2, b2);
    agg_kernel<true><<<(N_NODES * 32 + T - 1) / T, T>>>();

    // pooling: mean over each graph's contiguous node segment
    pool_kernel<<<NUM_GRAPHS, T>>>(out);
}

// round 14
// speedup vs baseline: 1.1906x; 1.1232x over previous
#include <cuda_runtime.h>
#include <cuda_fp16.h>
#include <mma.h>

using namespace nvcuda;

#define N_NODES    50000
#define N_EDGES    800000
#define IN_DIM     128
#define HID_DIM    64
#define OUT_DIM    64
#define NUM_GRAPHS 512
#define SCAN_T     1024

// ---------------- scratch (device globals; no allocations allowed) ----------------
__device__ __align__(16) int     g_degc  [N_NODES];        // per-dst edge count
__device__ __align__(16) int     g_cur   [N_NODES];        // fill cursor
__device__ __align__(16) int     g_row   [N_NODES + 1];    // CSR row offsets
__device__ __align__(16) float   g_dinv  [N_NODES];
__device__ __align__(16) int     g_srci  [N_EDGES];        // CSR payload: src index only
__device__ __align__(16) int     g_gstart[NUM_GRAPHS + 1]; // graph segment boundaries
__device__ __align__(16) __half2 g_hh    [N_NODES * 32];   // fp16 h = (A@W+b)*dinv[row]
__device__ __align__(16) float   g_agg1  [N_NODES * 64];   // relu(agg) layer 1 (fp32)
__device__ __align__(16) float   g_agg2  [N_NODES * 64];   // relu(agg) layer 2 (fp32)

// ---------------- prep kernels ----------------
__global__ void __launch_bounds__(256) count_kernel(const int* __restrict__ ei) {
    int e = blockIdx.x * blockDim.x + threadIdx.x;
    if (e >= N_EDGES) return;
    atomicAdd(&g_degc[ei[N_EDGES + e]], 1);
}

// single-block exclusive scan of g_degc -> g_row; also computes g_dinv.
__global__ void __launch_bounds__(SCAN_T) scan_kernel() {
    __shared__ int sp[SCAN_T];
    int t = threadIdx.x;
    const int C = (N_NODES + SCAN_T - 1) / SCAN_T;   // 49
    int beg = t * C;
    int end = min(beg + C, N_NODES);
    int sum = 0;
    for (int i = beg; i < end; i++) sum += g_degc[i];
    sp[t] = sum;
    __syncthreads();
    for (int off = 1; off < SCAN_T; off <<= 1) {
        int v = (t >= off) ? sp[t - off] : 0;
        __syncthreads();
        sp[t] += v;
        __syncthreads();
    }
    int excl = sp[t] - sum;
    for (int i = beg; i < end; i++) {
        int c = g_degc[i];
        g_row[i]  = excl;
        g_dinv[i] = rsqrtf(fmaxf((float)c, 1.0f));
        excl += c;
    }
    if (t == SCAN_T - 1) g_row[N_NODES] = sp[SCAN_T - 1];
}

// counting-sort fill: CSR payload = src only. Also graph boundaries from sorted batch.
__global__ void __launch_bounds__(256) fill_kernel(const int* __restrict__ ei,
                                                   const int* __restrict__ batch) {
    int e = blockIdx.x * blockDim.x + threadIdx.x;
    if (e < N_NODES) {
        int b  = batch[e];
        int bp = (e == 0) ? -1 : batch[e - 1];
        for (int g = bp + 1; g <= b; g++) g_gstart[g] = e;
        if (e == N_NODES - 1)
            for (int g = b + 1; g <= NUM_GRAPHS; g++) g_gstart[g] = N_NODES;
    }
    if (e >= N_EDGES) return;
    int s = ei[e];
    int d = ei[N_EDGES + e];
    int pos = g_row[d] + atomicAdd(&g_cur[d], 1);
    g_srci[pos] = s;
}

// ---------------- tensor-core GEMM ----------------
// g_hh[M,64](fp16) = ((A[M,KTOT](fp32->fp16) @ W[KTOT,64](fp16)) + bias) * dinv[row]
// Block tile 128x64, 8 warps x (16 rows x 64 cols), m16n16k16 HMMA, fp32 accum.
#define KC 64   // K chunk

template<int KTOT, bool A_IS_AGG1>
__global__ void __launch_bounds__(256) gemm_tc_kernel(const float* __restrict__ Ap,
                                                      const float* __restrict__ W,
                                                      const float* __restrict__ bias) {
    __shared__ union SM {
        struct { __half a[128 * 72]; __half w[KC * 72]; } in;   // pad stride 72
        float o[128 * 64];
    } sm;

    const float* A = A_IS_AGG1 ? g_agg1 : Ap;
    int tid  = threadIdx.x;
    int wid  = tid >> 5;          // 0..7 -> 16-row slice
    int row0 = blockIdx.x * 128;

    wmma::fragment<wmma::accumulator, 16, 16, 16, float> cf[4];
#pragma unroll
    for (int n = 0; n < 4; n++) wmma::fill_fragment(cf[n], 0.0f);

    for (int k0 = 0; k0 < KTOT; k0 += KC) {
        // fill sA: 128 rows x KC halves (convert fp32->fp16)
#pragma unroll
        for (int i = 0; i < 8; i++) {
            int idx = tid + i * 256;            // 0..2047
            int r   = idx >> 4;                 // 0..127
            int c4  = idx & 15;                 // 0..15 (float4 granule)
            float4 v = make_float4(0.f, 0.f, 0.f, 0.f);
            int gr = row0 + r;
            if (gr < N_NODES)
                v = *(const float4*)(A + (size_t)gr * KTOT + k0 + c4 * 4);
            __half2 h0 = __floats2half2_rn(v.x, v.y);
            __half2 h1 = __floats2half2_rn(v.z, v.w);
            *(uint2*)(sm.in.a + r * 72 + c4 * 4) =
                make_uint2(*(unsigned*)&h0, *(unsigned*)&h1);
        }
        // fill sW: KC rows x 64 halves
#pragma unroll
        for (int i = 0; i < 4; i++) {
            int idx = tid + i * 256;            // 0..1023
            int kr  = idx >> 4;                 // 0..63
            int c4  = idx & 15;
            float4 v = *(const float4*)(W + (size_t)(k0 + kr) * 64 + c4 * 4);
            __half2 h0 = __floats2half2_rn(v.x, v.y);
            __half2 h1 = __floats2half2_rn(v.z, v.w);
            *(uint2*)(sm.in.w + kr * 72 + c4 * 4) =
                make_uint2(*(unsigned*)&h0, *(unsigned*)&h1);
        }
        __syncthreads();

#pragma unroll
        for (int kk = 0; kk < KC / 16; kk++) {
            wmma::fragment<wmma::matrix_a, 16, 16, 16, __half, wmma::row_major> af;
            wmma::load_matrix_sync(af, sm.in.a + (wid * 16) * 72 + kk * 16, 72);
#pragma unroll
            for (int n = 0; n < 4; n++) {
                wmma::fragment<wmma::matrix_b, 16, 16, 16, __half, wmma::row_major> bf;
                wmma::load_matrix_sync(bf, sm.in.w + (kk * 16) * 72 + n * 16, 72);
                wmma::mma_sync(cf[n], af, bf, cf[n]);
            }
        }
        __syncthreads();   // before next chunk overwrites smem
    }

    // stage accumulators through smem
#pragma unroll
    for (int n = 0; n < 4; n++)
        wmma::store_matrix_sync(sm.o + (wid * 16) * 64 + n * 16, cf[n], 64,
                                wmma::mem_row_major);
    __syncthreads();

    // epilogue: bias + dinv scale, convert to fp16, write g_hh
#pragma unroll
    for (int i = 0; i < 8; i++) {
        int idx = tid + i * 256;                // 0..2047
        int r   = idx >> 4;                     // 0..127
        int c4  = idx & 15;
        int gr = row0 + r;
        if (gr < N_NODES) {
            float4 v  = *(const float4*)(sm.o + r * 64 + c4 * 4);
            float4 bv = *(const float4*)(bias + c4 * 4);
            float dv  = g_dinv[gr];
            __half2 h0 = __floats2half2_rn((v.x + bv.x) * dv, (v.y + bv.y) * dv);
            __half2 h1 = __floats2half2_rn((v.z + bv.z) * dv, (v.w + bv.w) * dv);
            *(uint2*)(g_hh + (size_t)gr * 32 + c4 * 2) =
                make_uint2(*(unsigned*)&h0, *(unsigned*)&h1);
        }
    }
}

// ---------------- pull aggregation ----------------
// one warp per node; lane owns 2 dims (half2 gather). 8-edge unroll (MLP=8).
// agg[n] = relu( dinv[n] * sum h[src_e] ).  No atomics, fp32 accumulation.
template<bool TO_AGG2>
__global__ void __launch_bounds__(256) agg_kernel() {
    int node = (blockIdx.x * 256 + threadIdx.x) >> 5;
    if (node >= N_NODES) return;
    int lane = threadIdx.x & 31;
    int s0 = g_row[node];
    int s1 = g_row[node + 1];

    float2 a0 = make_float2(0.f, 0.f);
    float2 a1 = make_float2(0.f, 0.f);
    float2 a2 = make_float2(0.f, 0.f);
    float2 a3 = make_float2(0.f, 0.f);
    int e = s0;
    for (; e + 7 < s1; e += 8) {
        int i0 = g_srci[e + 0];
        int i1 = g_srci[e + 1];
        int i2 = g_srci[e + 2];
        int i3 = g_srci[e + 3];
        int i4 = g_srci[e + 4];
        int i5 = g_srci[e + 5];
        int i6 = g_srci[e + 6];
        int i7 = g_srci[e + 7];
        float2 v0 = __half22float2(g_hh[(size_t)i0 * 32 + lane]);
        float2 v1 = __half22float2(g_hh[(size_t)i1 * 32 + lane]);
        float2 v2 = __half22float2(g_hh[(size_t)i2 * 32 + lane]);
        float2 v3 = __half22float2(g_hh[(size_t)i3 * 32 + lane]);
        float2 v4 = __half22float2(g_hh[(size_t)i4 * 32 + lane]);
        float2 v5 = __half22float2(g_hh[(size_t)i5 * 32 + lane]);
        float2 v6 = __half22float2(g_hh[(size_t)i6 * 32 + lane]);
        float2 v7 = __half22float2(g_hh[(size_t)i7 * 32 + lane]);
        a0.x += v0.x + v4.x; a0.y += v0.y + v4.y;
        a1.x += v1.x + v5.x; a1.y += v1.y + v5.y;
        a2.x += v2.x + v6.x; a2.y += v2.y + v6.y;
        a3.x += v3.x + v7.x; a3.y += v3.y + v7.y;
    }
    for (; e < s1; e++) {
        float2 v = __half22float2(g_hh[(size_t)g_srci[e] * 32 + lane]);
        a0.x += v.x; a0.y += v.y;
    }
    float dv = g_dinv[node];
    float sx = ((a0.x + a1.x) + (a2.x + a3.x)) * dv;
    float sy = ((a0.y + a1.y) + (a2.y + a3.y)) * dv;
    float2 r = make_float2(fmaxf(sx, 0.f), fmaxf(sy, 0.f));
    float* dst = TO_AGG2 ? g_agg2 : g_agg1;
    *(float2*)(dst + (size_t)node * 64 + lane * 2) = r;
}

// pooling: one block per graph over its contiguous node range; mean of g_agg2.
__global__ void __launch_bounds__(256) pool_kernel(float* __restrict__ out) {
    __shared__ float sm[256];
    int g = blockIdx.x;
    int t = threadIdx.x;
    int d = t & 63;
    int r = t >> 6;        // 0..3
    int s0 = g_gstart[g];
    int s1 = g_gstart[g + 1];
    float acc = 0.f;
    for (int n = s0 + r; n < s1; n += 4)
        acc += g_agg2[(size_t)n * 64 + d];
    sm[t] = acc;
    __syncthreads();
    if (t < 64) {
        float v = sm[t] + sm[t + 64] + sm[t + 128] + sm[t + 192];
        float c = (float)(s1 - s0);
        out[(size_t)g * 64 + t] = v / fmaxf(c, 1.0f);
    }
}

// ---------------- launch ----------------
extern "C" void kernel_launch(void* const* d_in, const int* in_sizes, int n_in,
                              void* d_out, int out_size) {
    // Identify inputs by element count (robust to metadata ordering).
    const float *x = nullptr, *W1 = nullptr, *b1 = nullptr, *W2 = nullptr, *b2 = nullptr;
    const int   *ei = nullptr, *batch = nullptr;
    for (int i = 0; i < n_in; i++) {
        switch (in_sizes[i]) {
            case N_NODES * IN_DIM:   x     = (const float*)d_in[i]; break;
            case 2 * N_EDGES:        ei    = (const int*)d_in[i];   break;
            case N_NODES:            batch = (const int*)d_in[i];   break;
            case IN_DIM * HID_DIM:   W1    = (const float*)d_in[i]; break;
            case HID_DIM * OUT_DIM:  W2    = (const float*)d_in[i]; break;
            case HID_DIM:
                if (!b1) b1 = (const float*)d_in[i];
                else     b2 = (const float*)d_in[i];
                break;
            default: break;
        }
    }
    float* out = (float*)d_out;

    // zero the atomic counters via memset (graph-capturable, no alloc)
    void *degc_ptr = nullptr, *cur_ptr = nullptr;
    cudaGetSymbolAddress(&degc_ptr, g_degc);
    cudaGetSymbolAddress(&cur_ptr,  g_cur);
    cudaMemsetAsync(degc_ptr, 0, N_NODES * sizeof(int));
    cudaMemsetAsync(cur_ptr,  0, N_NODES * sizeof(int));

    const int T = 256;
    count_kernel<<<(N_EDGES + T - 1) / T, T>>>(ei);
    scan_kernel <<<1, SCAN_T>>>();
    fill_kernel <<<(N_EDGES + T - 1) / T, T>>>(ei, batch);

    // layer 1: h = (x @ W1 + b1)*dinv (fp16, HMMA); agg1 = relu(dinv * pull-sum(h))
    gemm_tc_kernel<IN_DIM, false><<<(N_NODES + 127) / 128, T>>>(x, W1, b1);
    agg_kernel<false><<<(N_NODES * 32 + T - 1) / T, T>>>();

    // layer 2: h = (agg1 @ W2 + b2)*dinv (fp16, HMMA); agg2 = relu(dinv * pull-sum(h))
    gemm_tc_kernel<HID_DIM, true><<<(N_NODES + 127) / 128, T>>>(nullptr, W2, b2);
    agg_kernel<true><<<(N_NODES * 32 + T - 1) / T, T>>>();

    // pooling: mean over each graph's contiguous node segment
    pool_kernel<<<NUM_GRAPHS, T>>>(out);
}